// round 8
// baseline (speedup 1.0000x reference)
#include <cuda_runtime.h>

#define TT 1024

// Inter-layer activations (device globals: allowed scratch)
__device__ float g_h1[256u * 1024u * 32u];        // layer1 output  (33.5 MB)
__device__ float g_h2[256u * 1024u * 64u];        // layer2 output  (67 MB)
__device__ float g_xg3[(size_t)256 * 1024 * 512]; // layer3 input projection (512 MB)

typedef unsigned long long u64;

// ---------------- packed f32x2 helpers ----------------
__device__ __forceinline__ u64 ffma2(u64 a, u64 b, u64 c) {
    u64 d;
    asm("fma.rn.f32x2 %0, %1, %2, %3;" : "=l"(d) : "l"(a), "l"(b), "l"(c));
    return d;
}
__device__ __forceinline__ u64 pack2(float x, float y) {
    u64 r;
    asm("mov.b64 %0, {%1, %2};" : "=l"(r) : "f"(x), "f"(y));
    return r;
}
__device__ __forceinline__ float hsum2(u64 v) {
    float x, y;
    asm("mov.b64 {%0, %1}, %2;" : "=f"(x), "=f"(y) : "l"(v));
    return x + y;
}
__device__ __forceinline__ void unpack2(u64 v, float& x, float& y) {
    asm("mov.b64 {%0, %1}, %2;" : "=f"(x), "=f"(y) : "l"(v));
}
// ---------------- activations (proven: rel_err 4e-7) --------
__device__ __forceinline__ float rcpa(float x) {
    float r; asm("rcp.approx.f32 %0, %1;" : "=f"(r) : "f"(x)); return r;
}
__device__ __forceinline__ float sigf(float x)   { return rcpa(1.f + __expf(-x)); }
__device__ __forceinline__ float tanhf_(float x) { return 1.f - 2.f * rcpa(__expf(2.f * x) + 1.f); }

// ---------------- cluster helpers (all R4/R6-proven) ----------------
__device__ __forceinline__ unsigned smem_u32(const void* p) {
    return (unsigned)__cvta_generic_to_shared(p);
}
__device__ __forceinline__ unsigned mapa_u32(unsigned a, unsigned r) {
    unsigned o; asm("mapa.shared::cluster.u32 %0, %1, %2;" : "=r"(o) : "r"(a), "r"(r)); return o;
}
__device__ __forceinline__ void st_cluster(unsigned a, float v) {
    asm volatile("st.shared::cluster.f32 [%0], %1;" :: "r"(a), "f"(v) : "memory");
}
__device__ __forceinline__ void cluster_sync_() {
    asm volatile("barrier.cluster.arrive.aligned;" ::: "memory");
    asm volatile("barrier.cluster.wait.aligned;"   ::: "memory");
}
__device__ __forceinline__ unsigned ctarank_() {
    unsigned r; asm("mov.u32 %0, %%cluster_ctarank;" : "=r"(r)); return r;
}

// =======================================================================
// Layer 1: in=1, hid=32.  One WARP per batch element; zero barriers.
// 128 blocks x 64 threads. (unchanged, passed)
// =======================================================================
__global__ void __launch_bounds__(64, 1) lstm1_kernel(
    const float* __restrict__ x,    const float* __restrict__ w_ih,
    const float* __restrict__ w_hh, const float* __restrict__ b_ih,
    const float* __restrict__ b_hh)
{
    const int tid = threadIdx.x;
    const int j   = tid & 31;
    const int b   = blockIdx.x * 2 + (tid >> 5);

    u64 wif[32], wgo[32];
    #pragma unroll
    for (int k = 0; k < 32; k++) {
        wif[k] = pack2(w_hh[(0  + j) * 32 + k], w_hh[(32 + j) * 32 + k]);
        wgo[k] = pack2(w_hh[(64 + j) * 32 + k], w_hh[(96 + j) * 32 + k]);
    }
    const u64 bif  = pack2(b_ih[j]      + b_hh[j],      b_ih[32 + j] + b_hh[32 + j]);
    const u64 bgo  = pack2(b_ih[64 + j] + b_hh[64 + j], b_ih[96 + j] + b_hh[96 + j]);
    const u64 wiif = pack2(w_ih[j],      w_ih[32 + j]);
    const u64 wigo = pack2(w_ih[64 + j], w_ih[96 + j]);

    const float* __restrict__ xp = x + (size_t)b * TT;
    float* __restrict__ op = g_h1 + (size_t)b * TT * 32 + j;
    float h = 0.f, c = 0.f;
    float xt = xp[0];

    for (int t = 0; t < TT; t++) {
        float xn = (t + 1 < TT) ? xp[t + 1] : 0.f;
        u64 xtp = pack2(xt, xt);
        u64 aif = ffma2(wiif, xtp, bif);
        u64 ago = ffma2(wigo, xtp, bgo);
        #pragma unroll
        for (int k = 0; k < 32; k++) {
            float hk = __shfl_sync(0xffffffffu, h, k);
            u64 hkp = pack2(hk, hk);
            aif = ffma2(wif[k], hkp, aif);
            ago = ffma2(wgo[k], hkp, ago);
        }
        float gi, gf, gg, go;
        unpack2(aif, gi, gf);
        unpack2(ago, gg, go);
        c = sigf(gf) * c + sigf(gi) * tanhf_(gg);
        h = sigf(go) * tanhf_(c);
        op[(size_t)t * 32] = h;
        xt = xn;
    }
}

// =======================================================================
// Layer 2: in=32, hid=64.  ONE batch per CTA, 256 CTAs x 256 threads.
// (unchanged from R6, passed)
// =======================================================================
__global__ void __launch_bounds__(256, 2) lstm2_kernel(
    const float* __restrict__ w_ih, const float* __restrict__ w_hh,
    const float* __restrict__ b_ih, const float* __restrict__ b_hh)
{
    __shared__ __align__(16) float h_sm[2][64];
    __shared__ __align__(16) float x_sm[2][32];
    __shared__ float g_sm[256];
    const int tid = threadIdx.x;
    const int b   = blockIdx.x;

    u64 wh[32], wi[16];
    {
        const ulonglong2* wr = (const ulonglong2*)(w_hh + (size_t)tid * 64);
        #pragma unroll
        for (int q = 0; q < 16; q++) { ulonglong2 v = wr[q]; wh[2*q] = v.x; wh[2*q+1] = v.y; }
        const ulonglong2* wr2 = (const ulonglong2*)(w_ih + (size_t)tid * 32);
        #pragma unroll
        for (int q = 0; q < 8; q++)  { ulonglong2 v = wr2[q]; wi[2*q] = v.x; wi[2*q+1] = v.y; }
    }
    const float bs = b_ih[tid] + b_hh[tid];
    const float* __restrict__ xin = g_h1 + (size_t)b * TT * 32;
    float* __restrict__ op = g_h2 + (size_t)b * TT * 64;

    if (tid < 64) h_sm[0][tid] = 0.f;
    if (tid < 32) x_sm[0][tid] = xin[tid];
    float c = 0.f;
    __syncthreads();

    for (int t = 0; t < TT; t++) {
        const int p = t & 1, np = p ^ 1;
        float xn = 0.f;
        if (tid < 32 && t + 1 < TT) xn = xin[(size_t)(t + 1) * 32 + tid];

        u64 a = pack2(bs, 0.f);
        {
            const ulonglong2* xv = (const ulonglong2*)&x_sm[p][0];
            #pragma unroll
            for (int q = 0; q < 8; q++) {
                ulonglong2 v = xv[q];
                a = ffma2(wi[2*q], v.x, a); a = ffma2(wi[2*q+1], v.y, a);
            }
            const ulonglong2* hv = (const ulonglong2*)&h_sm[p][0];
            #pragma unroll
            for (int q = 0; q < 16; q++) {
                ulonglong2 v = hv[q];
                a = ffma2(wh[2*q], v.x, a); a = ffma2(wh[2*q+1], v.y, a);
            }
        }
        g_sm[tid] = hsum2(a);
        __syncthreads();
        if (tid < 64) {
            float gi = g_sm[tid],       gf = g_sm[64 + tid];
            float gg = g_sm[128 + tid], go = g_sm[192 + tid];
            c = sigf(gf) * c + sigf(gi) * tanhf_(gg);
            float h = sigf(go) * tanhf_(c);
            h_sm[np][tid] = h;
            op[(size_t)t * 64 + tid] = h;
        }
        if (tid < 32) x_sm[np][tid] = xn;
        __syncthreads();
    }
}

// =======================================================================
// xg3 GEMM (unchanged, passed)
// =======================================================================
__global__ void __launch_bounds__(256, 1) xg3_kernel(const float* __restrict__ w_ih)
{
    __shared__ __align__(16) float x_sm[64][64];
    const int tid = threadIdx.x;
    const int b   = blockIdx.y;
    const int t0  = blockIdx.x * 64;

    u64 wa[32], wb[32];
    {
        const ulonglong2* wr = (const ulonglong2*)(w_ih + (size_t)tid * 64);
        #pragma unroll
        for (int q = 0; q < 16; q++) { ulonglong2 v = wr[q]; wa[2*q] = v.x; wa[2*q+1] = v.y; }
        const ulonglong2* wr2 = (const ulonglong2*)(w_ih + (size_t)(tid + 256) * 64);
        #pragma unroll
        for (int q = 0; q < 16; q++) { ulonglong2 v = wr2[q]; wb[2*q] = v.x; wb[2*q+1] = v.y; }
    }
    {
        const float4* src = (const float4*)(g_h2 + (size_t)b * TT * 64 + (size_t)t0 * 64);
        float4* dst = (float4*)&x_sm[0][0];
        #pragma unroll
        for (int i = 0; i < 4; i++) dst[tid + 256 * i] = src[tid + 256 * i];
    }
    __syncthreads();

    float* outp = g_xg3 + ((size_t)b * TT + t0) * 512 + tid;
    for (int tk = 0; tk < 64; tk++) {
        const ulonglong2* xv = (const ulonglong2*)&x_sm[tk][0];
        u64 a0 = pack2(0.f, 0.f), a1 = a0;
        #pragma unroll
        for (int q = 0; q < 16; q++) {
            ulonglong2 v = xv[q];
            a0 = ffma2(wa[2*q], v.x, a0); a0 = ffma2(wa[2*q+1], v.y, a0);
            a1 = ffma2(wb[2*q], v.x, a1); a1 = ffma2(wb[2*q+1], v.y, a1);
        }
        outp[(size_t)tk * 512]       = hsum2(a0);
        outp[(size_t)tk * 512 + 256] = hsum2(a1);
    }
}

// =======================================================================
// Layer 3 v6: warp-local update.  64 clusters x 2 CTAs, 4 batches/cluster,
// 512 threads/CTA (16 warps), 1 CTA/SM.
//   Warp w owns unit-quad w: units rank*64 + w*4 .. +4 (16 gate rows).
//   Lane l: row r = l>>1 (gate r>>2, unit-in-quad r&3), K-half = l&1.
//   32 packed u64 weights/thread, 4 batch accumulators.
//   After FMA: shfl_xor(1) combines K-halves; 16 shfls gather the 4 gates of
//   (unit, batch) onto lane y<16 (y>>2 = batch, y&3 = unit); that lane runs the
//   activation chain, keeps c, writes h local + peer (st_cluster).
//   ONE barrier per step: barrier.cluster (doubles as CTA sync).
// =======================================================================
__global__ void __launch_bounds__(512, 1) __cluster_dims__(2, 1, 1) lstm3_kernel(
    const float* __restrict__ w_hh,
    const float* __restrict__ b_ih, const float* __restrict__ b_hh,
    const float* __restrict__ fc_w, const float* __restrict__ fc_b,
    float* __restrict__ out)
{
    __shared__ __align__(16) float h_sm[2][4][128];   // 4 KB, all 128 units
    __shared__ float pool_sm[4][128];                 // 2 KB (epilogue)

    const int tid  = threadIdx.x;
    const unsigned rank = ctarank_();
    const int bg0  = (blockIdx.x >> 1) * 4;
    const int wid  = tid >> 5;               // unit-quad 0..15
    const int lane = tid & 31;
    const int r    = lane >> 1;              // row within quad-block [0,16)
    const int half = lane & 1;               // K-half
    const int gate = r >> 2, x = r & 3;
    const int grow = gate * 128 + (int)rank * 64 + wid * 4 + x;  // global gate row

    u64 wh[32];
    {
        const ulonglong2* wr = (const ulonglong2*)(w_hh + (size_t)grow * 128 + half * 64);
        #pragma unroll
        for (int q = 0; q < 16; q++) { ulonglong2 v = wr[q]; wh[2*q] = v.x; wh[2*q+1] = v.y; }
    }

    // update role: lane y < 16 handles (batch y>>2, unit rank*64 + wid*4 + (y&3))
    const bool upd = (lane < 16);
    const int b_u = lane >> 2, ux = lane & 3;
    const int u   = (int)rank * 64 + wid * 4 + ux;
    float bs0 = 0.f, bs1 = 0.f, bs2 = 0.f, bs3 = 0.f;
    if (upd) {
        bs0 = b_ih[u]       + b_hh[u];
        bs1 = b_ih[128 + u] + b_hh[128 + u];
        bs2 = b_ih[256 + u] + b_hh[256 + u];
        bs3 = b_ih[384 + u] + b_hh[384 + u];
    }
    const float* __restrict__ xgp =
        g_xg3 + ((size_t)(bg0 + b_u) * TT) * 512 + u;

    unsigned la0 = smem_u32(&h_sm[0][b_u][u]);
    unsigned la1 = smem_u32(&h_sm[1][b_u][u]);
    unsigned pa0 = mapa_u32(la0, rank ^ 1u);
    unsigned pa1 = mapa_u32(la1, rank ^ 1u);

    for (int i = tid; i < 2 * 4 * 128; i += 512) ((float*)h_sm)[i] = 0.f;
    __syncthreads();
    cluster_sync_();   // zeroed h visible cluster-wide

    float c = 0.f, hsumv = 0.f;
    float x0 = 0.f, x1 = 0.f, x2 = 0.f, x3 = 0.f;
    if (upd) { x0 = xgp[0]; x1 = xgp[128]; x2 = xgp[256]; x3 = xgp[384]; }

    for (int t = 0; t < TT; t++) {
        const int p = t & 1;
        float n0 = 0.f, n1 = 0.f, n2 = 0.f, n3 = 0.f;
        if (upd && t + 1 < TT) {
            const size_t o = (size_t)(t + 1) * 512;
            n0 = xgp[o]; n1 = xgp[o + 128]; n2 = xgp[o + 256]; n3 = xgp[o + 384];
        }

        // FMA over own K-half for 4 batches
        u64 a0 = pack2(0.f, 0.f), a1 = a0, a2 = a0, a3 = a0;
        {
            const ulonglong2* hb = (const ulonglong2*)&h_sm[p][0][0] + half * 16;
            #pragma unroll
            for (int q = 0; q < 16; q++) {
                ulonglong2 v0 = hb[q], v1 = hb[32 + q], v2 = hb[64 + q], v3 = hb[96 + q];
                a0 = ffma2(wh[2*q], v0.x, a0); a0 = ffma2(wh[2*q+1], v0.y, a0);
                a1 = ffma2(wh[2*q], v1.x, a1); a1 = ffma2(wh[2*q+1], v1.y, a1);
                a2 = ffma2(wh[2*q], v2.x, a2); a2 = ffma2(wh[2*q+1], v2.y, a2);
                a3 = ffma2(wh[2*q], v3.x, a3); a3 = ffma2(wh[2*q+1], v3.y, a3);
            }
        }
        // combine K-halves across the lane pair
        float s0 = hsum2(a0), s1 = hsum2(a1), s2 = hsum2(a2), s3 = hsum2(a3);
        s0 += __shfl_xor_sync(0xffffffffu, s0, 1);
        s1 += __shfl_xor_sync(0xffffffffu, s1, 1);
        s2 += __shfl_xor_sync(0xffffffffu, s2, 1);
        s3 += __shfl_xor_sync(0xffffffffu, s3, 1);

        // gather the 4 gates of (batch b_u, unit ux) onto lane y
        float gv0, gv1, gv2, gv3;
        {
            const int sbase = (upd ? ux : 0) << 1;
            #define GATHER(gdst, g)                                              \
            {                                                                    \
                int src = sbase + ((g) << 3);                                    \
                float v0 = __shfl_sync(0xffffffffu, s0, src);                    \
                float v1 = __shfl_sync(0xffffffffu, s1, src);                    \
                float v2 = __shfl_sync(0xffffffffu, s2, src);                    \
                float v3 = __shfl_sync(0xffffffffu, s3, src);                    \
                float va = (b_u & 1) ? v1 : v0;                                  \
                float vb = (b_u & 1) ? v3 : v2;                                  \
                gdst = (b_u & 2) ? vb : va;                                      \
            }
            GATHER(gv0, 0) GATHER(gv1, 1) GATHER(gv2, 2) GATHER(gv3, 3)
            #undef GATHER
        }

        if (upd) {
            float g0 = gv0 + bs0 + x0;
            float g1 = gv1 + bs1 + x1;
            float g2 = gv2 + bs2 + x2;
            float g3 = gv3 + bs3 + x3;
            c = sigf(g1) * c + sigf(g0) * tanhf_(g2);
            float h = sigf(g3) * tanhf_(c);
            hsumv += h;
            if (p == 0) { h_sm[1][b_u][u] = h; st_cluster(pa1, h); }
            else        { h_sm[0][b_u][u] = h; st_cluster(pa0, h); }
            x0 = n0; x1 = n1; x2 = n2; x3 = n3;
        }
        cluster_sync_();   // sole per-step barrier: orders local + peer h stores
    }

    // epilogue: pooled mean -> rank 0's pool_sm -> FC on rank 0
    if (upd) {
        float pv = hsumv * (1.f / 1024.f);
        if (rank == 0) pool_sm[b_u][u] = pv;
        else           st_cluster(mapa_u32(smem_u32(&pool_sm[b_u][u]), 0u), pv);
    }
    cluster_sync_();
    if (rank == 0 && tid < 40) {
        const int b = tid / 10, m = tid % 10;
        float acc = fc_b[m];
        #pragma unroll 8
        for (int jj = 0; jj < 128; jj++)
            acc += pool_sm[b][jj] * fc_w[m * 128 + jj];
        out[(size_t)(bg0 + b) * 10 + m] = acc;
    }
    cluster_sync_();   // keep SMEM alive until FC reads complete
}

// =======================================================================
extern "C" void kernel_launch(void* const* d_in, const int* in_sizes, int n_in,
                              void* d_out, int out_size)
{
    const float* x     = (const float*)d_in[0];
    const float* w_ih1 = (const float*)d_in[1];
    const float* w_hh1 = (const float*)d_in[2];
    const float* b_ih1 = (const float*)d_in[3];
    const float* b_hh1 = (const float*)d_in[4];
    const float* w_ih2 = (const float*)d_in[5];
    const float* w_hh2 = (const float*)d_in[6];
    const float* b_ih2 = (const float*)d_in[7];
    const float* b_hh2 = (const float*)d_in[8];
    const float* w_ih3 = (const float*)d_in[9];
    const float* w_hh3 = (const float*)d_in[10];
    const float* b_ih3 = (const float*)d_in[11];
    const float* b_hh3 = (const float*)d_in[12];
    const float* fc_w  = (const float*)d_in[13];
    const float* fc_b  = (const float*)d_in[14];
    float* out = (float*)d_out;

    lstm1_kernel<<<128, 64>>>(x, w_ih1, w_hh1, b_ih1, b_hh1);
    lstm2_kernel<<<256, 256>>>(w_ih2, w_hh2, b_ih2, b_hh2);
    {
        dim3 grid(TT / 64, 256);
        xg3_kernel<<<grid, 256>>>(w_ih3);
    }
    lstm3_kernel<<<128, 512>>>(w_hh3, b_ih3, b_hh3, fc_w, fc_b, out);
}

// round 10
// speedup vs baseline: 1.2653x; 1.2653x over previous
#include <cuda_runtime.h>

#define TT 1024

// Inter-layer activations (device globals: allowed scratch)
__device__ float g_h1[256u * 1024u * 32u];        // layer1 output  (33.5 MB)
__device__ float g_h2[256u * 1024u * 64u];        // layer2 output  (67 MB)
__device__ float g_xg3[(size_t)256 * 1024 * 512]; // layer3 input proj + bias (512 MB)

typedef unsigned long long u64;

// ---------------- packed f32x2 helpers ----------------
__device__ __forceinline__ u64 ffma2(u64 a, u64 b, u64 c) {
    u64 d;
    asm("fma.rn.f32x2 %0, %1, %2, %3;" : "=l"(d) : "l"(a), "l"(b), "l"(c));
    return d;
}
__device__ __forceinline__ u64 pack2(float x, float y) {
    u64 r;
    asm("mov.b64 %0, {%1, %2};" : "=l"(r) : "f"(x), "f"(y));
    return r;
}
__device__ __forceinline__ float hsum2(u64 v) {
    float x, y;
    asm("mov.b64 {%0, %1}, %2;" : "=f"(x), "=f"(y) : "l"(v));
    return x + y;
}
__device__ __forceinline__ void unpack2(u64 v, float& x, float& y) {
    asm("mov.b64 {%0, %1}, %2;" : "=f"(x), "=f"(y) : "l"(v));
}
// ---------------- activations (proven: rel_err 4e-7) --------
__device__ __forceinline__ float rcpa(float x) {
    float r; asm("rcp.approx.f32 %0, %1;" : "=f"(r) : "f"(x)); return r;
}
__device__ __forceinline__ float sigf(float x)   { return rcpa(1.f + __expf(-x)); }
__device__ __forceinline__ float tanhf_(float x) { return 1.f - 2.f * rcpa(__expf(2.f * x) + 1.f); }

// ---------------- cluster helpers (R4/R6-proven) ----------------
__device__ __forceinline__ unsigned smem_u32(const void* p) {
    return (unsigned)__cvta_generic_to_shared(p);
}
__device__ __forceinline__ unsigned mapa_u32(unsigned a, unsigned r) {
    unsigned o; asm("mapa.shared::cluster.u32 %0, %1, %2;" : "=r"(o) : "r"(a), "r"(r)); return o;
}
__device__ __forceinline__ void st_cluster(unsigned a, float v) {
    asm volatile("st.shared::cluster.f32 [%0], %1;" :: "r"(a), "f"(v) : "memory");
}
__device__ __forceinline__ void cluster_sync_() {
    asm volatile("barrier.cluster.arrive.aligned;" ::: "memory");
    asm volatile("barrier.cluster.wait.aligned;"   ::: "memory");
}
__device__ __forceinline__ unsigned ctarank_() {
    unsigned r; asm("mov.u32 %0, %%cluster_ctarank;" : "=r"(r)); return r;
}

// =======================================================================
// Layer 1: in=1, hid=32.  One WARP per batch element; zero barriers.
// 128 blocks x 64 threads. (passed R5/R6)
// =======================================================================
__global__ void __launch_bounds__(64, 1) lstm1_kernel(
    const float* __restrict__ x,    const float* __restrict__ w_ih,
    const float* __restrict__ w_hh, const float* __restrict__ b_ih,
    const float* __restrict__ b_hh)
{
    const int tid = threadIdx.x;
    const int j   = tid & 31;
    const int b   = blockIdx.x * 2 + (tid >> 5);

    u64 wif[32], wgo[32];
    #pragma unroll
    for (int k = 0; k < 32; k++) {
        wif[k] = pack2(w_hh[(0  + j) * 32 + k], w_hh[(32 + j) * 32 + k]);
        wgo[k] = pack2(w_hh[(64 + j) * 32 + k], w_hh[(96 + j) * 32 + k]);
    }
    const u64 bif  = pack2(b_ih[j]      + b_hh[j],      b_ih[32 + j] + b_hh[32 + j]);
    const u64 bgo  = pack2(b_ih[64 + j] + b_hh[64 + j], b_ih[96 + j] + b_hh[96 + j]);
    const u64 wiif = pack2(w_ih[j],      w_ih[32 + j]);
    const u64 wigo = pack2(w_ih[64 + j], w_ih[96 + j]);

    const float* __restrict__ xp = x + (size_t)b * TT;
    float* __restrict__ op = g_h1 + (size_t)b * TT * 32 + j;
    float h = 0.f, c = 0.f;
    float xt = xp[0];

    for (int t = 0; t < TT; t++) {
        float xn = (t + 1 < TT) ? xp[t + 1] : 0.f;
        u64 xtp = pack2(xt, xt);
        u64 aif = ffma2(wiif, xtp, bif);
        u64 ago = ffma2(wigo, xtp, bgo);
        #pragma unroll
        for (int k = 0; k < 32; k++) {
            float hk = __shfl_sync(0xffffffffu, h, k);
            u64 hkp = pack2(hk, hk);
            aif = ffma2(wif[k], hkp, aif);
            ago = ffma2(wgo[k], hkp, ago);
        }
        float gi, gf, gg, go;
        unpack2(aif, gi, gf);
        unpack2(ago, gg, go);
        c = sigf(gf) * c + sigf(gi) * tanhf_(gg);
        h = sigf(go) * tanhf_(c);
        op[(size_t)t * 32] = h;
        xt = xn;
    }
}

// =======================================================================
// Layer 2: in=32, hid=64.  ONE batch per CTA, 256 CTAs x 256 threads.
// (passed R6)
// =======================================================================
__global__ void __launch_bounds__(256, 2) lstm2_kernel(
    const float* __restrict__ w_ih, const float* __restrict__ w_hh,
    const float* __restrict__ b_ih, const float* __restrict__ b_hh)
{
    __shared__ __align__(16) float h_sm[2][64];
    __shared__ __align__(16) float x_sm[2][32];
    __shared__ float g_sm[256];
    const int tid = threadIdx.x;
    const int b   = blockIdx.x;

    u64 wh[32], wi[16];
    {
        const ulonglong2* wr = (const ulonglong2*)(w_hh + (size_t)tid * 64);
        #pragma unroll
        for (int q = 0; q < 16; q++) { ulonglong2 v = wr[q]; wh[2*q] = v.x; wh[2*q+1] = v.y; }
        const ulonglong2* wr2 = (const ulonglong2*)(w_ih + (size_t)tid * 32);
        #pragma unroll
        for (int q = 0; q < 8; q++)  { ulonglong2 v = wr2[q]; wi[2*q] = v.x; wi[2*q+1] = v.y; }
    }
    const float bs = b_ih[tid] + b_hh[tid];
    const float* __restrict__ xin = g_h1 + (size_t)b * TT * 32;
    float* __restrict__ op = g_h2 + (size_t)b * TT * 64;

    if (tid < 64) h_sm[0][tid] = 0.f;
    if (tid < 32) x_sm[0][tid] = xin[tid];
    float c = 0.f;
    __syncthreads();

    for (int t = 0; t < TT; t++) {
        const int p = t & 1, np = p ^ 1;
        float xn = 0.f;
        if (tid < 32 && t + 1 < TT) xn = xin[(size_t)(t + 1) * 32 + tid];

        u64 a = pack2(bs, 0.f);
        {
            const ulonglong2* xv = (const ulonglong2*)&x_sm[p][0];
            #pragma unroll
            for (int q = 0; q < 8; q++) {
                ulonglong2 v = xv[q];
                a = ffma2(wi[2*q], v.x, a); a = ffma2(wi[2*q+1], v.y, a);
            }
            const ulonglong2* hv = (const ulonglong2*)&h_sm[p][0];
            #pragma unroll
            for (int q = 0; q < 16; q++) {
                ulonglong2 v = hv[q];
                a = ffma2(wh[2*q], v.x, a); a = ffma2(wh[2*q+1], v.y, a);
            }
        }
        g_sm[tid] = hsum2(a);
        __syncthreads();
        if (tid < 64) {
            float gi = g_sm[tid],       gf = g_sm[64 + tid];
            float gg = g_sm[128 + tid], go = g_sm[192 + tid];
            c = sigf(gf) * c + sigf(gi) * tanhf_(gg);
            float h = sigf(go) * tanhf_(c);
            h_sm[np][tid] = h;
            op[(size_t)t * 64 + tid] = h;
        }
        if (tid < 32) x_sm[np][tid] = xn;
        __syncthreads();
    }
}

// =======================================================================
// xg3 GEMM + BIAS FOLD: xg3[b][t][g] = sum_k h2[b][t][k]*w_ih3[g][k] + bias[g]
// =======================================================================
__global__ void __launch_bounds__(256, 1) xg3_kernel(
    const float* __restrict__ w_ih,
    const float* __restrict__ b_ih, const float* __restrict__ b_hh)
{
    __shared__ __align__(16) float x_sm[64][64];
    const int tid = threadIdx.x;
    const int b   = blockIdx.y;
    const int t0  = blockIdx.x * 64;

    u64 wa[32], wb[32];
    {
        const ulonglong2* wr = (const ulonglong2*)(w_ih + (size_t)tid * 64);
        #pragma unroll
        for (int q = 0; q < 16; q++) { ulonglong2 v = wr[q]; wa[2*q] = v.x; wa[2*q+1] = v.y; }
        const ulonglong2* wr2 = (const ulonglong2*)(w_ih + (size_t)(tid + 256) * 64);
        #pragma unroll
        for (int q = 0; q < 16; q++) { ulonglong2 v = wr2[q]; wb[2*q] = v.x; wb[2*q+1] = v.y; }
    }
    const float bsA = b_ih[tid]       + b_hh[tid];
    const float bsB = b_ih[tid + 256] + b_hh[tid + 256];
    {
        const float4* src = (const float4*)(g_h2 + (size_t)b * TT * 64 + (size_t)t0 * 64);
        float4* dst = (float4*)&x_sm[0][0];
        #pragma unroll
        for (int i = 0; i < 4; i++) dst[tid + 256 * i] = src[tid + 256 * i];
    }
    __syncthreads();

    float* outp = g_xg3 + ((size_t)b * TT + t0) * 512 + tid;
    for (int tk = 0; tk < 64; tk++) {
        const ulonglong2* xv = (const ulonglong2*)&x_sm[tk][0];
        u64 a0 = pack2(0.f, 0.f), a1 = a0;
        #pragma unroll
        for (int q = 0; q < 16; q++) {
            ulonglong2 v = xv[q];
            a0 = ffma2(wa[2*q], v.x, a0); a0 = ffma2(wa[2*q+1], v.y, a0);
            a1 = ffma2(wb[2*q], v.x, a1); a1 = ffma2(wb[2*q+1], v.y, a1);
        }
        outp[(size_t)tk * 512]       = hsum2(a0) + bsA;
        outp[(size_t)tk * 512 + 256] = hsum2(a1) + bsB;
    }
}

// =======================================================================
// Layer 3 v8: R4 skeleton (sync: __syncthreads + barrier.cluster ONLY) with
//  - unit-major psum [batch][slot][2] -> updater reads 4 contiguous LDS.128
//  - updates distributed over lanes 0-15 of ALL 16 warps
//  - bias pre-folded into g_xg3
// 64 clusters x 2 CTAs, 4 batches/cluster, 512 threads/CTA, 1 CTA/SM.
// =======================================================================
__global__ void __launch_bounds__(512, 1) __cluster_dims__(2, 1, 1) lstm3_kernel(
    const float* __restrict__ w_hh,
    const float* __restrict__ fc_w, const float* __restrict__ fc_b,
    float* __restrict__ out)
{
    __shared__ __align__(16) float h_sm[2][4][128];   // 4 KB double-buffered
    __shared__ __align__(16) u64 psum[4][256][2];     // [batch][slot][half] 16 KB
    __shared__ float pool_sm[4][128];                 // 2 KB (epilogue)

    const int tid  = threadIdx.x;
    const unsigned rank = ctarank_();
    const int bg0  = (blockIdx.x >> 1) * 4;
    const int half = tid >> 8;                  // K-half (warp-uniform)
    const int slot = tid & 255;
    const int lu   = slot >> 2;                 // local unit 0..63 (unit-major)
    const int gate = slot & 3;
    const int grow = gate * 128 + (int)rank * 64 + lu;   // global gate row

    u64 wh[32];
    {
        const ulonglong2* wr = (const ulonglong2*)(w_hh + (size_t)grow * 128 + half * 64);
        #pragma unroll
        for (int q = 0; q < 16; q++) { ulonglong2 v = wr[q]; wh[2*q] = v.x; wh[2*q+1] = v.y; }
    }

    // distributed update role: warp wrp lane l<16 -> update idx = wrp*16+l
    const int wrp  = tid >> 5;
    const int lane = tid & 31;
    const bool upd = (lane < 16);
    const int idx  = wrp * 16 + lane;          // 0..255 over upd threads
    const int ub   = idx >> 6;                 // batch 0..3
    const int ulu  = idx & 63;                 // local unit 0..63
    const int ug   = (int)rank * 64 + ulu;     // global unit

    const float* __restrict__ xgp =
        g_xg3 + ((size_t)(bg0 + ub) * TT) * 512 + ug;

    unsigned la0 = smem_u32(&h_sm[0][ub][ug]);
    unsigned la1 = smem_u32(&h_sm[1][ub][ug]);
    unsigned pa0 = mapa_u32(la0, rank ^ 1u);
    unsigned pa1 = mapa_u32(la1, rank ^ 1u);

    for (int i = tid; i < 2 * 4 * 128; i += 512) ((float*)h_sm)[i] = 0.f;
    __syncthreads();
    cluster_sync_();   // zeroed h visible cluster-wide

    float c = 0.f, hsumv = 0.f;
    float x0 = 0.f, x1 = 0.f, x2 = 0.f, x3 = 0.f;
    if (upd) { x0 = xgp[0]; x1 = xgp[128]; x2 = xgp[256]; x3 = xgp[384]; }

    for (int t = 0; t < TT; t++) {
        const int p = t & 1;
        float n0 = 0.f, n1 = 0.f, n2 = 0.f, n3 = 0.f;
        if (upd && t + 1 < TT) {
            const size_t o = (size_t)(t + 1) * 512;
            n0 = xgp[o]; n1 = xgp[o + 128]; n2 = xgp[o + 256]; n3 = xgp[o + 384];
        }

        // FMA over own K-half for 4 batches (h broadcast loads)  [R4-identical]
        u64 a0 = pack2(0.f, 0.f), a1 = a0, a2 = a0, a3 = a0;
        {
            const ulonglong2* hb = (const ulonglong2*)&h_sm[p][0][0] + half * 16;
            #pragma unroll
            for (int q = 0; q < 16; q++) {
                ulonglong2 v0 = hb[q], v1 = hb[32 + q], v2 = hb[64 + q], v3 = hb[96 + q];
                a0 = ffma2(wh[2*q], v0.x, a0); a0 = ffma2(wh[2*q+1], v0.y, a0);
                a1 = ffma2(wh[2*q], v1.x, a1); a1 = ffma2(wh[2*q+1], v1.y, a1);
                a2 = ffma2(wh[2*q], v2.x, a2); a2 = ffma2(wh[2*q+1], v2.y, a2);
                a3 = ffma2(wh[2*q], v3.x, a3); a3 = ffma2(wh[2*q+1], v3.y, a3);
            }
        }
        psum[0][slot][half] = a0;
        psum[1][slot][half] = a1;
        psum[2][slot][half] = a2;
        psum[3][slot][half] = a3;
        __syncthreads();   // psum(t) complete

        if (upd) {
            const ulonglong2* pp = (const ulonglong2*)&psum[ub][ulu * 4][0];
            ulonglong2 q0 = pp[0], q1 = pp[1], q2 = pp[2], q3 = pp[3];
            float g0 = hsum2(q0.x) + hsum2(q0.y) + x0;   // i
            float g1 = hsum2(q1.x) + hsum2(q1.y) + x1;   // f
            float g2 = hsum2(q2.x) + hsum2(q2.y) + x2;   // g
            float g3 = hsum2(q3.x) + hsum2(q3.y) + x3;   // o
            c = sigf(g1) * c + sigf(g0) * tanhf_(g2);
            float h = sigf(g3) * tanhf_(c);
            hsumv += h;
            if (p == 0) { h_sm[1][ub][ug] = h; st_cluster(pa1, h); }
            else        { h_sm[0][ub][ug] = h; st_cluster(pa0, h); }
            x0 = n0; x1 = n1; x2 = n2; x3 = n3;
        }
        cluster_sync_();   // sole global sync: orders local + peer h stores
    }

    // epilogue: pooled mean -> rank 0's pool_sm -> FC on rank 0
    if (upd) {
        float pv = hsumv * (1.f / 1024.f);
        if (rank == 0) pool_sm[ub][ug] = pv;
        else           st_cluster(mapa_u32(smem_u32(&pool_sm[ub][ug]), 0u), pv);
    }
    cluster_sync_();
    if (rank == 0 && tid < 40) {
        const int b = tid / 10, m = tid % 10;
        float acc = fc_b[m];
        #pragma unroll 8
        for (int jj = 0; jj < 128; jj++)
            acc += pool_sm[b][jj] * fc_w[m * 128 + jj];
        out[(size_t)(bg0 + b) * 10 + m] = acc;
    }
    cluster_sync_();   // keep SMEM alive until FC reads complete
}

// =======================================================================
extern "C" void kernel_launch(void* const* d_in, const int* in_sizes, int n_in,
                              void* d_out, int out_size)
{
    const float* x     = (const float*)d_in[0];
    const float* w_ih1 = (const float*)d_in[1];
    const float* w_hh1 = (const float*)d_in[2];
    const float* b_ih1 = (const float*)d_in[3];
    const float* b_hh1 = (const float*)d_in[4];
    const float* w_ih2 = (const float*)d_in[5];
    const float* w_hh2 = (const float*)d_in[6];
    const float* b_ih2 = (const float*)d_in[7];
    const float* b_hh2 = (const float*)d_in[8];
    const float* w_ih3 = (const float*)d_in[9];
    const float* w_hh3 = (const float*)d_in[10];
    const float* b_ih3 = (const float*)d_in[11];
    const float* b_hh3 = (const float*)d_in[12];
    const float* fc_w  = (const float*)d_in[13];
    const float* fc_b  = (const float*)d_in[14];
    float* out = (float*)d_out;

    lstm1_kernel<<<128, 64>>>(x, w_ih1, w_hh1, b_ih1, b_hh1);
    lstm2_kernel<<<256, 256>>>(w_ih2, w_hh2, b_ih2, b_hh2);
    {
        dim3 grid(TT / 64, 256);
        xg3_kernel<<<grid, 256>>>(w_ih3, b_ih3, b_hh3);
    }
    lstm3_kernel<<<128, 512>>>(w_hh3, fc_w, fc_b, out);
}

// round 11
// speedup vs baseline: 1.3775x; 1.0887x over previous
#include <cuda_runtime.h>

#define TT 1024

// Inter-layer activations (device globals: allowed scratch)
__device__ float g_h1[256u * 1024u * 32u];        // layer1 output  (33.5 MB)
__device__ float g_h2[256u * 1024u * 64u];        // layer2 output  (67 MB)
__device__ float g_xg3[(size_t)256 * 1024 * 512]; // layer3 input proj + bias (512 MB)

typedef unsigned long long u64;

// ---------------- packed f32x2 helpers ----------------
__device__ __forceinline__ u64 ffma2(u64 a, u64 b, u64 c) {
    u64 d;
    asm("fma.rn.f32x2 %0, %1, %2, %3;" : "=l"(d) : "l"(a), "l"(b), "l"(c));
    return d;
}
__device__ __forceinline__ u64 pack2(float x, float y) {
    u64 r;
    asm("mov.b64 %0, {%1, %2};" : "=l"(r) : "f"(x), "f"(y));
    return r;
}
__device__ __forceinline__ float hsum2(u64 v) {
    float x, y;
    asm("mov.b64 {%0, %1}, %2;" : "=f"(x), "=f"(y) : "l"(v));
    return x + y;
}
__device__ __forceinline__ void unpack2(u64 v, float& x, float& y) {
    asm("mov.b64 {%0, %1}, %2;" : "=f"(x), "=f"(y) : "l"(v));
}
// ---------------- activations (proven: rel_err 4e-7) --------
__device__ __forceinline__ float rcpa(float x) {
    float r; asm("rcp.approx.f32 %0, %1;" : "=f"(r) : "f"(x)); return r;
}
__device__ __forceinline__ float sigf(float x)   { return rcpa(1.f + __expf(-x)); }
__device__ __forceinline__ float tanhf_(float x) { return 1.f - 2.f * rcpa(__expf(2.f * x) + 1.f); }

// ---------------- cluster helpers (R4/R6-proven) ----------------
__device__ __forceinline__ unsigned smem_u32(const void* p) {
    return (unsigned)__cvta_generic_to_shared(p);
}
__device__ __forceinline__ unsigned mapa_u32(unsigned a, unsigned r) {
    unsigned o; asm("mapa.shared::cluster.u32 %0, %1, %2;" : "=r"(o) : "r"(a), "r"(r)); return o;
}
__device__ __forceinline__ void st_cluster(unsigned a, float v) {
    asm volatile("st.shared::cluster.f32 [%0], %1;" :: "r"(a), "f"(v) : "memory");
}
__device__ __forceinline__ void cluster_sync_() {
    asm volatile("barrier.cluster.arrive.aligned;" ::: "memory");
    asm volatile("barrier.cluster.wait.aligned;"   ::: "memory");
}
__device__ __forceinline__ unsigned ctarank_() {
    unsigned r; asm("mov.u32 %0, %%cluster_ctarank;" : "=r"(r)); return r;
}

// =======================================================================
// Layer 1: in=1, hid=32.  One WARP per batch element; zero barriers.
// 128 blocks x 64 threads. (passed R5/R6/R8/R10)
// =======================================================================
__global__ void __launch_bounds__(64, 1) lstm1_kernel(
    const float* __restrict__ x,    const float* __restrict__ w_ih,
    const float* __restrict__ w_hh, const float* __restrict__ b_ih,
    const float* __restrict__ b_hh)
{
    const int tid = threadIdx.x;
    const int j   = tid & 31;
    const int b   = blockIdx.x * 2 + (tid >> 5);

    u64 wif[32], wgo[32];
    #pragma unroll
    for (int k = 0; k < 32; k++) {
        wif[k] = pack2(w_hh[(0  + j) * 32 + k], w_hh[(32 + j) * 32 + k]);
        wgo[k] = pack2(w_hh[(64 + j) * 32 + k], w_hh[(96 + j) * 32 + k]);
    }
    const u64 bif  = pack2(b_ih[j]      + b_hh[j],      b_ih[32 + j] + b_hh[32 + j]);
    const u64 bgo  = pack2(b_ih[64 + j] + b_hh[64 + j], b_ih[96 + j] + b_hh[96 + j]);
    const u64 wiif = pack2(w_ih[j],      w_ih[32 + j]);
    const u64 wigo = pack2(w_ih[64 + j], w_ih[96 + j]);

    const float* __restrict__ xp = x + (size_t)b * TT;
    float* __restrict__ op = g_h1 + (size_t)b * TT * 32 + j;
    float h = 0.f, c = 0.f;
    float xt = xp[0];

    for (int t = 0; t < TT; t++) {
        float xn = (t + 1 < TT) ? xp[t + 1] : 0.f;
        u64 xtp = pack2(xt, xt);
        u64 aif = ffma2(wiif, xtp, bif);
        u64 ago = ffma2(wigo, xtp, bgo);
        #pragma unroll
        for (int k = 0; k < 32; k++) {
            float hk = __shfl_sync(0xffffffffu, h, k);
            u64 hkp = pack2(hk, hk);
            aif = ffma2(wif[k], hkp, aif);
            ago = ffma2(wgo[k], hkp, ago);
        }
        float gi, gf, gg, go;
        unpack2(aif, gi, gf);
        unpack2(ago, gg, go);
        c = sigf(gf) * c + sigf(gi) * tanhf_(gg);
        h = sigf(go) * tanhf_(c);
        op[(size_t)t * 32] = h;
        xt = xn;
    }
}

// =======================================================================
// Layer 2 v3: in=32, hid=64.  ONE batch per CTA, 256 CTAs x 256 threads,
// 2 CTAs/SM.  Thread -> (unit u = tid>>2, gate = tid&3): a unit's 4 gates
// sit in adjacent lanes.  Update is warp-local: each lane activates its own
// gate, 3 shfls deliver (i,g,o) to the f-lane which owns c and writes h.
// ONE __syncthreads per step; no g_sm round trip.
// =======================================================================
__global__ void __launch_bounds__(256, 2) lstm2_kernel(
    const float* __restrict__ w_ih, const float* __restrict__ w_hh,
    const float* __restrict__ b_ih, const float* __restrict__ b_hh)
{
    __shared__ __align__(16) float h_sm[2][64];
    __shared__ __align__(16) float x_sm[2][32];
    const int tid  = threadIdx.x;
    const int b    = blockIdx.x;
    const int u    = tid >> 2;         // unit 0..63
    const int gate = tid & 3;          // 0=i 1=f 2=g 3=o
    const int r    = gate * 64 + u;    // weight row
    const int gl   = (tid & 31) & ~3;  // group base lane within warp

    u64 wh[32], wi[16];
    {
        const ulonglong2* wr = (const ulonglong2*)(w_hh + (size_t)r * 64);
        #pragma unroll
        for (int q = 0; q < 16; q++) { ulonglong2 v = wr[q]; wh[2*q] = v.x; wh[2*q+1] = v.y; }
        const ulonglong2* wr2 = (const ulonglong2*)(w_ih + (size_t)r * 32);
        #pragma unroll
        for (int q = 0; q < 8; q++)  { ulonglong2 v = wr2[q]; wi[2*q] = v.x; wi[2*q+1] = v.y; }
    }
    const float bs = b_ih[r] + b_hh[r];
    const float* __restrict__ xin = g_h1 + (size_t)b * TT * 32;
    float* __restrict__ op = g_h2 + (size_t)b * TT * 64;

    if (tid < 64) h_sm[0][tid] = 0.f;
    if (tid < 32) x_sm[0][tid] = xin[tid];
    float c = 0.f;
    __syncthreads();

    for (int t = 0; t < TT; t++) {
        const int p = t & 1, np = p ^ 1;
        float xn = 0.f;
        if (tid < 32 && t + 1 < TT) xn = xin[(size_t)(t + 1) * 32 + tid];

        u64 a = pack2(bs, 0.f);
        {
            const ulonglong2* xv = (const ulonglong2*)&x_sm[p][0];
            #pragma unroll
            for (int q = 0; q < 8; q++) {
                ulonglong2 v = xv[q];
                a = ffma2(wi[2*q], v.x, a); a = ffma2(wi[2*q+1], v.y, a);
            }
            const ulonglong2* hv = (const ulonglong2*)&h_sm[p][0];
            #pragma unroll
            for (int q = 0; q < 16; q++) {
                ulonglong2 v = hv[q];
                a = ffma2(wh[2*q], v.x, a); a = ffma2(wh[2*q+1], v.y, a);
            }
        }
        float g = hsum2(a);
        // distributed activation: i,f,o -> sigmoid; g -> tanh
        float act = (gate == 2) ? tanhf_(g) : sigf(g);
        // deliver i, g, o to the f-lane of the 4-lane group
        float vi = __shfl_sync(0xffffffffu, act, gl + 0);
        float vg = __shfl_sync(0xffffffffu, act, gl + 2);
        float vo = __shfl_sync(0xffffffffu, act, gl + 3);
        if (gate == 1) {
            c = act * c + vi * vg;         // act == sigf(f)
            float h = vo * tanhf_(c);
            h_sm[np][u] = h;
            op[(size_t)t * 64 + u] = h;
        }
        if (tid < 32) x_sm[np][tid] = xn;
        __syncthreads();                   // sole barrier per step
    }
}

// =======================================================================
// xg3 GEMM + BIAS FOLD: xg3[b][t][g] = sum_k h2[b][t][k]*w_ih3[g][k] + bias[g]
// (passed R10)
// =======================================================================
__global__ void __launch_bounds__(256, 1) xg3_kernel(
    const float* __restrict__ w_ih,
    const float* __restrict__ b_ih, const float* __restrict__ b_hh)
{
    __shared__ __align__(16) float x_sm[64][64];
    const int tid = threadIdx.x;
    const int b   = blockIdx.y;
    const int t0  = blockIdx.x * 64;

    u64 wa[32], wb[32];
    {
        const ulonglong2* wr = (const ulonglong2*)(w_ih + (size_t)tid * 64);
        #pragma unroll
        for (int q = 0; q < 16; q++) { ulonglong2 v = wr[q]; wa[2*q] = v.x; wa[2*q+1] = v.y; }
        const ulonglong2* wr2 = (const ulonglong2*)(w_ih + (size_t)(tid + 256) * 64);
        #pragma unroll
        for (int q = 0; q < 16; q++) { ulonglong2 v = wr2[q]; wb[2*q] = v.x; wb[2*q+1] = v.y; }
    }
    const float bsA = b_ih[tid]       + b_hh[tid];
    const float bsB = b_ih[tid + 256] + b_hh[tid + 256];
    {
        const float4* src = (const float4*)(g_h2 + (size_t)b * TT * 64 + (size_t)t0 * 64);
        float4* dst = (float4*)&x_sm[0][0];
        #pragma unroll
        for (int i = 0; i < 4; i++) dst[tid + 256 * i] = src[tid + 256 * i];
    }
    __syncthreads();

    float* outp = g_xg3 + ((size_t)b * TT + t0) * 512 + tid;
    for (int tk = 0; tk < 64; tk++) {
        const ulonglong2* xv = (const ulonglong2*)&x_sm[tk][0];
        u64 a0 = pack2(0.f, 0.f), a1 = a0;
        #pragma unroll
        for (int q = 0; q < 16; q++) {
            ulonglong2 v = xv[q];
            a0 = ffma2(wa[2*q], v.x, a0); a0 = ffma2(wa[2*q+1], v.y, a0);
            a1 = ffma2(wb[2*q], v.x, a1); a1 = ffma2(wb[2*q+1], v.y, a1);
        }
        outp[(size_t)tk * 512]       = hsum2(a0) + bsA;
        outp[(size_t)tk * 512 + 256] = hsum2(a1) + bsB;
    }
}

// =======================================================================
// Layer 3: EXACT R4 revert (proven 1.775 ms), bias pre-folded into g_xg3.
// 64 clusters x 2 CTAs, 4 batches/cluster, 512 threads/CTA, 1 CTA/SM.
// Warps 0-7 K-half 0, warps 8-15 K-half 1; psum[4][256][2] gate-major
// (updater reads 16B @ 16B stride: conflict-free). Updaters = tid<256.
// Sync per step: __syncthreads (psum RAW) + barrier.cluster (h RAW).
// =======================================================================
__global__ void __launch_bounds__(512, 1) __cluster_dims__(2, 1, 1) lstm3_kernel(
    const float* __restrict__ w_hh,
    const float* __restrict__ fc_w, const float* __restrict__ fc_b,
    float* __restrict__ out)
{
    __shared__ __align__(16) float h_sm[2][4][128];   // 4 KB
    __shared__ __align__(16) u64 psum[4][256][2];     // [batch][slot][half] 16 KB
    const int tid  = threadIdx.x;
    const unsigned rank = ctarank_();
    const int bg0  = (blockIdx.x >> 1) * 4;
    const int half = tid >> 8;            // warp-uniform K-half
    const int slot = tid & 255;
    const int gate = slot >> 6, jl = slot & 63;
    const int grow = gate * 128 + (int)rank * 64 + jl;

    u64 wh[32];
    {
        const ulonglong2* wr = (const ulonglong2*)(w_hh + (size_t)grow * 128 + half * 64);
        #pragma unroll
        for (int q = 0; q < 16; q++) { ulonglong2 v = wr[q]; wh[2*q] = v.x; wh[2*q+1] = v.y; }
    }

    // updater role (tid < 256): batch ub, unit rank*64+uj  (bias folded in xg)
    const bool upd = (tid < 256);
    const int ub = (tid >> 6) & 3, uj = tid & 63;
    const float* __restrict__ xgp =
        g_xg3 + ((size_t)(bg0 + ub) * TT) * 512 + (size_t)rank * 64 + uj;

    unsigned la0 = smem_u32(&h_sm[0][ub][(int)rank * 64 + uj]);
    unsigned la1 = smem_u32(&h_sm[1][ub][(int)rank * 64 + uj]);
    unsigned pa0 = mapa_u32(la0, rank ^ 1u);
    unsigned pa1 = mapa_u32(la1, rank ^ 1u);

    for (int i = tid; i < 4 * 128; i += 512) ((float*)h_sm[0])[i] = 0.f;
    float c = 0.f, hsum = 0.f;
    float x0 = 0.f, x1 = 0.f, x2 = 0.f, x3 = 0.f;
    if (upd) { x0 = xgp[0]; x1 = xgp[128]; x2 = xgp[256]; x3 = xgp[384]; }
    __syncthreads();
    cluster_sync_();

    for (int t = 0; t < TT; t++) {
        const int p = t & 1;
        // prefetch next step's xg (latency hidden under the FMA block)
        float n0 = 0.f, n1 = 0.f, n2 = 0.f, n3 = 0.f;
        if (upd && t + 1 < TT) {
            const size_t o = (size_t)(t + 1) * 512;
            n0 = xgp[o]; n1 = xgp[o + 128]; n2 = xgp[o + 256]; n3 = xgp[o + 384];
        }

        u64 a0 = pack2(0.f, 0.f), a1 = a0, a2 = a0, a3 = a0;
        {
            // hvb: batch stride = 128 floats = 32 ulonglong2; half offset = 16
            const ulonglong2* hvb = (const ulonglong2*)&h_sm[p][0][0] + half * 16;
            #pragma unroll
            for (int q = 0; q < 16; q++) {
                ulonglong2 v0 = hvb[q], v1 = hvb[32 + q], v2 = hvb[64 + q], v3 = hvb[96 + q];
                a0 = ffma2(wh[2*q], v0.x, a0); a0 = ffma2(wh[2*q+1], v0.y, a0);
                a1 = ffma2(wh[2*q], v1.x, a1); a1 = ffma2(wh[2*q+1], v1.y, a1);
                a2 = ffma2(wh[2*q], v2.x, a2); a2 = ffma2(wh[2*q+1], v2.y, a2);
                a3 = ffma2(wh[2*q], v3.x, a3); a3 = ffma2(wh[2*q+1], v3.y, a3);
            }
        }
        psum[0][slot][half] = a0;
        psum[1][slot][half] = a1;
        psum[2][slot][half] = a2;
        psum[3][slot][half] = a3;
        __syncthreads();

        if (upd) {
            const ulonglong2* ps = (const ulonglong2*)&psum[ub][0][0];
            ulonglong2 q0 = ps[0   + uj], q1 = ps[64  + uj];
            ulonglong2 q2 = ps[128 + uj], q3 = ps[192 + uj];
            float g0 = hsum2(q0.x) + hsum2(q0.y) + x0;
            float g1 = hsum2(q1.x) + hsum2(q1.y) + x1;
            float g2 = hsum2(q2.x) + hsum2(q2.y) + x2;
            float g3 = hsum2(q3.x) + hsum2(q3.y) + x3;
            c = sigf(g1) * c + sigf(g0) * tanhf_(g2);
            float h = sigf(g3) * tanhf_(c);
            hsum += h;
            if (p == 0) { h_sm[1][ub][(int)rank * 64 + uj] = h; st_cluster(pa1, h); }
            else        { h_sm[0][ub][(int)rank * 64 + uj] = h; st_cluster(pa0, h); }
            x0 = n0; x1 = n1; x2 = n2; x3 = n3;
        }
        cluster_sync_();
    }

    // epilogue: pooled mean -> both CTAs' SMEM -> FC on rank 0
    if (upd) {
        float pv = hsum * (1.f / 1024.f);
        h_sm[0][ub][(int)rank * 64 + uj] = pv;
        st_cluster(pa0, pv);
    }
    cluster_sync_();
    if (rank == 0 && tid < 40) {
        const int b = tid / 10, m = tid % 10;
        float acc = fc_b[m];
        #pragma unroll 8
        for (int jj = 0; jj < 128; jj++)
            acc += h_sm[0][b][jj] * fc_w[m * 128 + jj];
        out[(size_t)(bg0 + b) * 10 + m] = acc;
    }
    cluster_sync_();   // keep SMEM alive until FC reads complete
}

// =======================================================================
extern "C" void kernel_launch(void* const* d_in, const int* in_sizes, int n_in,
                              void* d_out, int out_size)
{
    const float* x     = (const float*)d_in[0];
    const float* w_ih1 = (const float*)d_in[1];
    const float* w_hh1 = (const float*)d_in[2];
    const float* b_ih1 = (const float*)d_in[3];
    const float* b_hh1 = (const float*)d_in[4];
    const float* w_ih2 = (const float*)d_in[5];
    const float* w_hh2 = (const float*)d_in[6];
    const float* b_ih2 = (const float*)d_in[7];
    const float* b_hh2 = (const float*)d_in[8];
    const float* w_ih3 = (const float*)d_in[9];
    const float* w_hh3 = (const float*)d_in[10];
    const float* b_ih3 = (const float*)d_in[11];
    const float* b_hh3 = (const float*)d_in[12];
    const float* fc_w  = (const float*)d_in[13];
    const float* fc_b  = (const float*)d_in[14];
    float* out = (float*)d_out;

    lstm1_kernel<<<128, 64>>>(x, w_ih1, w_hh1, b_ih1, b_hh1);
    lstm2_kernel<<<256, 256>>>(w_ih2, w_hh2, b_ih2, b_hh2);
    {
        dim3 grid(TT / 64, 256);
        xg3_kernel<<<grid, 256>>>(w_ih3, b_ih3, b_hh3);
    }
    lstm3_kernel<<<128, 512>>>(w_hh3, fc_w, fc_b, out);
}

// round 12
// speedup vs baseline: 1.4084x; 1.0224x over previous
#include <cuda_runtime.h>

#define TT 1024

// Inter-layer activations (device globals: allowed scratch)
__device__ float g_h1[256u * 1024u * 32u];        // layer1 output  (33.5 MB)
__device__ float g_h2[256u * 1024u * 64u];        // layer2 output  (67 MB)
__device__ float g_xg3[(size_t)256 * 1024 * 512]; // layer3 input proj + bias (512 MB)

typedef unsigned long long u64;

// ---------------- packed f32x2 helpers ----------------
__device__ __forceinline__ u64 ffma2(u64 a, u64 b, u64 c) {
    u64 d;
    asm("fma.rn.f32x2 %0, %1, %2, %3;" : "=l"(d) : "l"(a), "l"(b), "l"(c));
    return d;
}
__device__ __forceinline__ u64 pack2(float x, float y) {
    u64 r;
    asm("mov.b64 %0, {%1, %2};" : "=l"(r) : "f"(x), "f"(y));
    return r;
}
__device__ __forceinline__ float hsum2(u64 v) {
    float x, y;
    asm("mov.b64 {%0, %1}, %2;" : "=f"(x), "=f"(y) : "l"(v));
    return x + y;
}
__device__ __forceinline__ void unpack2(u64 v, float& x, float& y) {
    asm("mov.b64 {%0, %1}, %2;" : "=f"(x), "=f"(y) : "l"(v));
}
// ---------------- activations (proven: rel_err 4e-7) --------
__device__ __forceinline__ float rcpa(float x) {
    float r; asm("rcp.approx.f32 %0, %1;" : "=f"(r) : "f"(x)); return r;
}
__device__ __forceinline__ float sigf(float x)   { return rcpa(1.f + __expf(-x)); }
__device__ __forceinline__ float tanhf_(float x) { return 1.f - 2.f * rcpa(__expf(2.f * x) + 1.f); }

// ---------------- cluster helpers (R4/R6-proven) ----------------
__device__ __forceinline__ unsigned smem_u32(const void* p) {
    return (unsigned)__cvta_generic_to_shared(p);
}
__device__ __forceinline__ unsigned mapa_u32(unsigned a, unsigned r) {
    unsigned o; asm("mapa.shared::cluster.u32 %0, %1, %2;" : "=r"(o) : "r"(a), "r"(r)); return o;
}
__device__ __forceinline__ void st_cluster(unsigned a, float v) {
    asm volatile("st.shared::cluster.f32 [%0], %1;" :: "r"(a), "f"(v) : "memory");
}
__device__ __forceinline__ void cluster_sync_() {
    asm volatile("barrier.cluster.arrive.aligned;" ::: "memory");
    asm volatile("barrier.cluster.wait.aligned;"   ::: "memory");
}
__device__ __forceinline__ unsigned ctarank_() {
    unsigned r; asm("mov.u32 %0, %%cluster_ctarank;" : "=r"(r)); return r;
}

// =======================================================================
// Layer 1 v2: in=1, hid=32.  One WARP per batch; zero barriers.
// 4 accumulator chains (2 per gate-pair) to halve the dependent-FMA depth.
// 128 blocks x 64 threads.
// =======================================================================
__global__ void __launch_bounds__(64, 1) lstm1_kernel(
    const float* __restrict__ x,    const float* __restrict__ w_ih,
    const float* __restrict__ w_hh, const float* __restrict__ b_ih,
    const float* __restrict__ b_hh)
{
    const int tid = threadIdx.x;
    const int j   = tid & 31;
    const int b   = blockIdx.x * 2 + (tid >> 5);

    u64 wif[32], wgo[32];
    #pragma unroll
    for (int k = 0; k < 32; k++) {
        wif[k] = pack2(w_hh[(0  + j) * 32 + k], w_hh[(32 + j) * 32 + k]);
        wgo[k] = pack2(w_hh[(64 + j) * 32 + k], w_hh[(96 + j) * 32 + k]);
    }
    const u64 bif  = pack2(b_ih[j]      + b_hh[j],      b_ih[32 + j] + b_hh[32 + j]);
    const u64 bgo  = pack2(b_ih[64 + j] + b_hh[64 + j], b_ih[96 + j] + b_hh[96 + j]);
    const u64 wiif = pack2(w_ih[j],      w_ih[32 + j]);
    const u64 wigo = pack2(w_ih[64 + j], w_ih[96 + j]);

    const float* __restrict__ xp = x + (size_t)b * TT;
    float* __restrict__ op = g_h1 + (size_t)b * TT * 32 + j;
    float h = 0.f, c = 0.f;
    float xt = xp[0];

    for (int t = 0; t < TT; t++) {
        float xn = (t + 1 < TT) ? xp[t + 1] : 0.f;
        u64 xtp = pack2(xt, xt);
        u64 aif0 = ffma2(wiif, xtp, bif);
        u64 ago0 = ffma2(wigo, xtp, bgo);
        u64 aif1 = pack2(0.f, 0.f), ago1 = aif1;
        #pragma unroll
        for (int k = 0; k < 16; k++) {
            float hk  = __shfl_sync(0xffffffffu, h, k);
            float hk2 = __shfl_sync(0xffffffffu, h, k + 16);
            u64 hp  = pack2(hk,  hk);
            u64 hp2 = pack2(hk2, hk2);
            aif0 = ffma2(wif[k],      hp,  aif0);
            ago0 = ffma2(wgo[k],      hp,  ago0);
            aif1 = ffma2(wif[k + 16], hp2, aif1);
            ago1 = ffma2(wgo[k + 16], hp2, ago1);
        }
        float i0, f0, i1, f1, g0, o0, g1, o1;
        unpack2(aif0, i0, f0); unpack2(aif1, i1, f1);
        unpack2(ago0, g0, o0); unpack2(ago1, g1, o1);
        float gi = i0 + i1, gf = f0 + f1, gg = g0 + g1, go = o0 + o1;
        c = sigf(gf) * c + sigf(gi) * tanhf_(gg);
        h = sigf(go) * tanhf_(c);
        op[(size_t)t * 32] = h;
        xt = xn;
    }
}

// =======================================================================
// Layer 2: in=32, hid=64.  ONE batch per CTA, 256 CTAs x 256 threads.
// (R6/R10 proven version)
// =======================================================================
__global__ void __launch_bounds__(256, 2) lstm2_kernel(
    const float* __restrict__ w_ih, const float* __restrict__ w_hh,
    const float* __restrict__ b_ih, const float* __restrict__ b_hh)
{
    __shared__ __align__(16) float h_sm[2][64];
    __shared__ __align__(16) float x_sm[2][32];
    __shared__ float g_sm[256];
    const int tid = threadIdx.x;
    const int b   = blockIdx.x;

    u64 wh[32], wi[16];
    {
        const ulonglong2* wr = (const ulonglong2*)(w_hh + (size_t)tid * 64);
        #pragma unroll
        for (int q = 0; q < 16; q++) { ulonglong2 v = wr[q]; wh[2*q] = v.x; wh[2*q+1] = v.y; }
        const ulonglong2* wr2 = (const ulonglong2*)(w_ih + (size_t)tid * 32);
        #pragma unroll
        for (int q = 0; q < 8; q++)  { ulonglong2 v = wr2[q]; wi[2*q] = v.x; wi[2*q+1] = v.y; }
    }
    const float bs = b_ih[tid] + b_hh[tid];
    const float* __restrict__ xin = g_h1 + (size_t)b * TT * 32;
    float* __restrict__ op = g_h2 + (size_t)b * TT * 64;

    if (tid < 64) h_sm[0][tid] = 0.f;
    if (tid < 32) x_sm[0][tid] = xin[tid];
    float c = 0.f;
    __syncthreads();

    for (int t = 0; t < TT; t++) {
        const int p = t & 1, np = p ^ 1;
        float xn = 0.f;
        if (tid < 32 && t + 1 < TT) xn = xin[(size_t)(t + 1) * 32 + tid];

        u64 a = pack2(bs, 0.f);
        {
            const ulonglong2* xv = (const ulonglong2*)&x_sm[p][0];
            #pragma unroll
            for (int q = 0; q < 8; q++) {
                ulonglong2 v = xv[q];
                a = ffma2(wi[2*q], v.x, a); a = ffma2(wi[2*q+1], v.y, a);
            }
            const ulonglong2* hv = (const ulonglong2*)&h_sm[p][0];
            #pragma unroll
            for (int q = 0; q < 16; q++) {
                ulonglong2 v = hv[q];
                a = ffma2(wh[2*q], v.x, a); a = ffma2(wh[2*q+1], v.y, a);
            }
        }
        g_sm[tid] = hsum2(a);
        __syncthreads();
        if (tid < 64) {
            float gi = g_sm[tid],       gf = g_sm[64 + tid];
            float gg = g_sm[128 + tid], go = g_sm[192 + tid];
            c = sigf(gf) * c + sigf(gi) * tanhf_(gg);
            float h = sigf(go) * tanhf_(c);
            h_sm[np][tid] = h;
            op[(size_t)t * 64 + tid] = h;
        }
        if (tid < 32) x_sm[np][tid] = xn;
        __syncthreads();
    }
}

// =======================================================================
// xg3 GEMM v2 + BIAS FOLD: 128-thread blocks (3 CTAs/SM) for latency cover.
// Block (tx, b, z): tokens [tx*64,+64), rows [z*256 + tid, z*256 + tid + 128].
// xg3[b][t][g] = sum_k h2[b][t][k]*w_ih3[g][k] + bias[g]
// =======================================================================
__global__ void __launch_bounds__(128, 3) xg3_kernel(
    const float* __restrict__ w_ih,
    const float* __restrict__ b_ih, const float* __restrict__ b_hh)
{
    __shared__ __align__(16) float x_sm[64][64];   // 16 KB
    const int tid = threadIdx.x;
    const int b   = blockIdx.y;
    const int t0  = blockIdx.x * 64;
    const int r0  = blockIdx.z * 256 + tid;        // first owned row
    const int r1  = r0 + 128;                      // second owned row

    u64 wa[32], wb[32];
    {
        const ulonglong2* wr = (const ulonglong2*)(w_ih + (size_t)r0 * 64);
        #pragma unroll
        for (int q = 0; q < 16; q++) { ulonglong2 v = wr[q]; wa[2*q] = v.x; wa[2*q+1] = v.y; }
        const ulonglong2* wr2 = (const ulonglong2*)(w_ih + (size_t)r1 * 64);
        #pragma unroll
        for (int q = 0; q < 16; q++) { ulonglong2 v = wr2[q]; wb[2*q] = v.x; wb[2*q+1] = v.y; }
    }
    const float bsA = b_ih[r0] + b_hh[r0];
    const float bsB = b_ih[r1] + b_hh[r1];
    {
        const float4* src = (const float4*)(g_h2 + (size_t)b * TT * 64 + (size_t)t0 * 64);
        float4* dst = (float4*)&x_sm[0][0];
        #pragma unroll
        for (int i = 0; i < 8; i++) dst[tid + 128 * i] = src[tid + 128 * i];
    }
    __syncthreads();

    float* outp = g_xg3 + ((size_t)b * TT + t0) * 512 + blockIdx.z * 256 + tid;
    for (int tk = 0; tk < 64; tk++) {
        const ulonglong2* xv = (const ulonglong2*)&x_sm[tk][0];
        u64 a0 = pack2(0.f, 0.f), a1 = a0;
        #pragma unroll
        for (int q = 0; q < 16; q++) {
            ulonglong2 v = xv[q];
            a0 = ffma2(wa[2*q], v.x, a0); a0 = ffma2(wa[2*q+1], v.y, a0);
            a1 = ffma2(wb[2*q], v.x, a1); a1 = ffma2(wb[2*q+1], v.y, a1);
        }
        outp[(size_t)tk * 512]       = hsum2(a0) + bsA;
        outp[(size_t)tk * 512 + 128] = hsum2(a1) + bsB;
    }
}

// =======================================================================
// Layer 3: EXACT R4/R11 structure (proven 1.78-1.83 ms), bias folded in xg3.
// 64 clusters x 2 CTAs, 4 batches/cluster, 512 threads/CTA, 1 CTA/SM.
// =======================================================================
__global__ void __launch_bounds__(512, 1) __cluster_dims__(2, 1, 1) lstm3_kernel(
    const float* __restrict__ w_hh,
    const float* __restrict__ fc_w, const float* __restrict__ fc_b,
    float* __restrict__ out)
{
    __shared__ __align__(16) float h_sm[2][4][128];   // 4 KB
    __shared__ __align__(16) u64 psum[4][256][2];     // [batch][slot][half] 16 KB
    const int tid  = threadIdx.x;
    const unsigned rank = ctarank_();
    const int bg0  = (blockIdx.x >> 1) * 4;
    const int half = tid >> 8;            // warp-uniform K-half
    const int slot = tid & 255;
    const int gate = slot >> 6, jl = slot & 63;
    const int grow = gate * 128 + (int)rank * 64 + jl;

    u64 wh[32];
    {
        const ulonglong2* wr = (const ulonglong2*)(w_hh + (size_t)grow * 128 + half * 64);
        #pragma unroll
        for (int q = 0; q < 16; q++) { ulonglong2 v = wr[q]; wh[2*q] = v.x; wh[2*q+1] = v.y; }
    }

    const bool upd = (tid < 256);
    const int ub = (tid >> 6) & 3, uj = tid & 63;
    const float* __restrict__ xgp =
        g_xg3 + ((size_t)(bg0 + ub) * TT) * 512 + (size_t)rank * 64 + uj;

    unsigned la0 = smem_u32(&h_sm[0][ub][(int)rank * 64 + uj]);
    unsigned la1 = smem_u32(&h_sm[1][ub][(int)rank * 64 + uj]);
    unsigned pa0 = mapa_u32(la0, rank ^ 1u);
    unsigned pa1 = mapa_u32(la1, rank ^ 1u);

    for (int i = tid; i < 4 * 128; i += 512) ((float*)h_sm[0])[i] = 0.f;
    float c = 0.f, hsum = 0.f;
    float x0 = 0.f, x1 = 0.f, x2 = 0.f, x3 = 0.f;
    if (upd) { x0 = xgp[0]; x1 = xgp[128]; x2 = xgp[256]; x3 = xgp[384]; }
    __syncthreads();
    cluster_sync_();

    for (int t = 0; t < TT; t++) {
        const int p = t & 1;
        float n0 = 0.f, n1 = 0.f, n2 = 0.f, n3 = 0.f;
        if (upd && t + 1 < TT) {
            const size_t o = (size_t)(t + 1) * 512;
            n0 = xgp[o]; n1 = xgp[o + 128]; n2 = xgp[o + 256]; n3 = xgp[o + 384];
        }

        u64 a0 = pack2(0.f, 0.f), a1 = a0, a2 = a0, a3 = a0;
        {
            const ulonglong2* hvb = (const ulonglong2*)&h_sm[p][0][0] + half * 16;
            #pragma unroll
            for (int q = 0; q < 16; q++) {
                ulonglong2 v0 = hvb[q], v1 = hvb[32 + q], v2 = hvb[64 + q], v3 = hvb[96 + q];
                a0 = ffma2(wh[2*q], v0.x, a0); a0 = ffma2(wh[2*q+1], v0.y, a0);
                a1 = ffma2(wh[2*q], v1.x, a1); a1 = ffma2(wh[2*q+1], v1.y, a1);
                a2 = ffma2(wh[2*q], v2.x, a2); a2 = ffma2(wh[2*q+1], v2.y, a2);
                a3 = ffma2(wh[2*q], v3.x, a3); a3 = ffma2(wh[2*q+1], v3.y, a3);
            }
        }
        psum[0][slot][half] = a0;
        psum[1][slot][half] = a1;
        psum[2][slot][half] = a2;
        psum[3][slot][half] = a3;
        __syncthreads();

        if (upd) {
            const ulonglong2* ps = (const ulonglong2*)&psum[ub][0][0];
            ulonglong2 q0 = ps[0   + uj], q1 = ps[64  + uj];
            ulonglong2 q2 = ps[128 + uj], q3 = ps[192 + uj];
            float g0 = hsum2(q0.x) + hsum2(q0.y) + x0;
            float g1 = hsum2(q1.x) + hsum2(q1.y) + x1;
            float g2 = hsum2(q2.x) + hsum2(q2.y) + x2;
            float g3 = hsum2(q3.x) + hsum2(q3.y) + x3;
            c = sigf(g1) * c + sigf(g0) * tanhf_(g2);
            float h = sigf(g3) * tanhf_(c);
            hsum += h;
            if (p == 0) { h_sm[1][ub][(int)rank * 64 + uj] = h; st_cluster(pa1, h); }
            else        { h_sm[0][ub][(int)rank * 64 + uj] = h; st_cluster(pa0, h); }
            x0 = n0; x1 = n1; x2 = n2; x3 = n3;
        }
        cluster_sync_();
    }

    // epilogue: pooled mean -> both CTAs' SMEM -> FC on rank 0
    if (upd) {
        float pv = hsum * (1.f / 1024.f);
        h_sm[0][ub][(int)rank * 64 + uj] = pv;
        st_cluster(pa0, pv);
    }
    cluster_sync_();
    if (rank == 0 && tid < 40) {
        const int b = tid / 10, m = tid % 10;
        float acc = fc_b[m];
        #pragma unroll 8
        for (int jj = 0; jj < 128; jj++)
            acc += h_sm[0][b][jj] * fc_w[m * 128 + jj];
        out[(size_t)(bg0 + b) * 10 + m] = acc;
    }
    cluster_sync_();   // keep SMEM alive until FC reads complete
}

// =======================================================================
extern "C" void kernel_launch(void* const* d_in, const int* in_sizes, int n_in,
                              void* d_out, int out_size)
{
    const float* x     = (const float*)d_in[0];
    const float* w_ih1 = (const float*)d_in[1];
    const float* w_hh1 = (const float*)d_in[2];
    const float* b_ih1 = (const float*)d_in[3];
    const float* b_hh1 = (const float*)d_in[4];
    const float* w_ih2 = (const float*)d_in[5];
    const float* w_hh2 = (const float*)d_in[6];
    const float* b_ih2 = (const float*)d_in[7];
    const float* b_hh2 = (const float*)d_in[8];
    const float* w_ih3 = (const float*)d_in[9];
    const float* w_hh3 = (const float*)d_in[10];
    const float* b_ih3 = (const float*)d_in[11];
    const float* b_hh3 = (const float*)d_in[12];
    const float* fc_w  = (const float*)d_in[13];
    const float* fc_b  = (const float*)d_in[14];
    float* out = (float*)d_out;

    lstm1_kernel<<<128, 64>>>(x, w_ih1, w_hh1, b_ih1, b_hh1);
    lstm2_kernel<<<256, 256>>>(w_ih2, w_hh2, b_ih2, b_hh2);
    {
        dim3 grid(TT / 64, 256, 2);
        xg3_kernel<<<grid, 128>>>(w_ih3, b_ih3, b_hh3);
    }
    lstm3_kernel<<<128, 512>>>(w_hh3, fc_w, fc_b, out);
}